// round 2
// baseline (speedup 1.0000x reference)
#include <cuda_runtime.h>
#include <cstdint>
#include <cstddef>

#define BB 512
#define TT 1024
#define II 64
#define HH 10
#define GG 40

// Scratch: gate pre-activations for layer 1 and layer 2 (pre-scaled: 0.5x for
// sigmoid rows i/f/o, 1.0x for tanh rows g). ~84 MB each, static device arrays
// (no allocations allowed).
__device__ float g_xg1[(size_t)BB * TT * GG];
__device__ float g_xg2[(size_t)BB * TT * GG];

// ---------------------------------------------------------------------------
// Kernel 1: xg1[b,t,g] = scale(g) * (bias_ih[g]+bias_hh[g] + sum_d x[b,t,d]*Wih1[g,d])
// Thread per (b,t) row. W transposed+prescaled in smem, broadcast LDS.128 reads.
// ---------------------------------------------------------------------------
__global__ void __launch_bounds__(128) xg1_kernel(
    const float* __restrict__ x,
    const float* __restrict__ Wih1,
    const float* __restrict__ bih1,
    const float* __restrict__ bhh1)
{
    __shared__ float Wt[II * GG];   // Wt[d*GG + g]
    __shared__ float bs[GG];
    int tid = threadIdx.x;
    for (int i = tid; i < II * GG; i += 128) {
        int d = i / GG, g = i % GG;
        float s = (g >= 20 && g < 30) ? 1.0f : 0.5f;   // g-gate rows: no prescale
        Wt[i] = Wih1[g * II + d] * s;
    }
    if (tid < GG) {
        float s = (tid >= 20 && tid < 30) ? 1.0f : 0.5f;
        bs[tid] = (bih1[tid] + bhh1[tid]) * s;
    }
    __syncthreads();

    size_t row = (size_t)blockIdx.x * 128 + tid;       // < 524288 exactly
    const float4* xr = (const float4*)(x + row * II);

    float acc[GG];
#pragma unroll
    for (int g = 0; g < GG; g++) acc[g] = bs[g];

#pragma unroll 4
    for (int d4 = 0; d4 < II / 4; d4++) {
        float4 xv = xr[d4];
#pragma unroll
        for (int k = 0; k < 4; k++) {
            float xs = (k == 0) ? xv.x : (k == 1) ? xv.y : (k == 2) ? xv.z : xv.w;
            const float4* wr = (const float4*)(Wt + (d4 * 4 + k) * GG);
#pragma unroll
            for (int g4 = 0; g4 < GG / 4; g4++) {
                float4 w = wr[g4];
                acc[g4 * 4 + 0] = fmaf(xs, w.x, acc[g4 * 4 + 0]);
                acc[g4 * 4 + 1] = fmaf(xs, w.y, acc[g4 * 4 + 1]);
                acc[g4 * 4 + 2] = fmaf(xs, w.z, acc[g4 * 4 + 2]);
                acc[g4 * 4 + 3] = fmaf(xs, w.w, acc[g4 * 4 + 3]);
            }
        }
    }

    float4* o = (float4*)(g_xg1 + row * GG);
#pragma unroll
    for (int g4 = 0; g4 < GG / 4; g4++)
        o[g4] = make_float4(acc[g4 * 4 + 0], acc[g4 * 4 + 1],
                            acc[g4 * 4 + 2], acc[g4 * 4 + 3]);
}

// ---------------------------------------------------------------------------
// Accurate activations. inv1pe2(v) = 1/(1+exp(2v)).
//   sigmoid(pre) with prescaled arg a=0.5*pre:  1 - inv1pe2(a)
//   tanh(x):                                    1 - 2*inv1pe2(x)
// ---------------------------------------------------------------------------
__device__ __forceinline__ float inv1pe2(float v)
{
    float e = __expf(2.0f * v);            // inf/0 saturate correctly
    return __fdividef(1.0f, e + 1.0f);
}

// ---------------------------------------------------------------------------
// Kernel 2: warp-per-batch sequential scan, layer1 -> (xg2 produced on the fly)
// -> layer2 -> fused fc1/fc2 epilogue.
// Lane L (<20) owns gate rows L (i/f) and L+20 (g/o). h replicated per lane,
// c_j owned by lane j. 10-shuffle h broadcast per step.
// ---------------------------------------------------------------------------
__global__ void __launch_bounds__(128) scan_kernel(
    const float* __restrict__ h0,   const float* __restrict__ c0,
    const float* __restrict__ Whh1, const float* __restrict__ Wih2,
    const float* __restrict__ Whh2, const float* __restrict__ bih2,
    const float* __restrict__ bhh2, const float* __restrict__ fc1w,
    const float* __restrict__ fc1b, const float* __restrict__ fc2w,
    const float* __restrict__ fc2b, float* __restrict__ out)
{
    const int warp = threadIdx.x >> 5;
    const int lane = threadIdx.x & 31;
    const int b = blockIdx.x * 4 + warp;           // 128 blocks x 4 warps = 512
    const int L = lane;
    const int row0 = (L < 20) ? L : 0;             // lanes >=20 shadow lane 0
    const int row1 = row0 + 20;
    const float s0 = 0.5f;                         // row0 is i or f -> sigmoid
    const float s1 = (L < 10) ? 1.0f : 0.5f;       // row1: g (tanh) or o (sigmoid)

    float w1a[HH], w1b[HH], w2a[HH], w2b[HH], wi2a[HH], wi2b[HH];
#pragma unroll
    for (int j = 0; j < HH; j++) {
        w1a[j]  = Whh1[row0 * HH + j] * s0;
        w1b[j]  = Whh1[row1 * HH + j] * s1;
        w2a[j]  = Whh2[row0 * HH + j] * s0;
        w2b[j]  = Whh2[row1 * HH + j] * s1;
        wi2a[j] = Wih2[row0 * HH + j] * s0;
        wi2b[j] = Wih2[row1 * HH + j] * s1;
    }
    const float b2a = (bih2[row0] + bhh2[row0]) * s0;
    const float b2b = (bih2[row1] + bhh2[row1]) * s1;

    float h[HH], cown;
#pragma unroll
    for (int j = 0; j < HH; j++) h[j] = h0[b * HH + j];
    cown = (L < HH) ? c0[b * HH + L] : 0.0f;

    const float* xg1p = g_xg1 + (size_t)b * TT * GG;
    float*       xg2p = g_xg2 + (size_t)b * TT * GG;

    float bufA[4], bufB[4];
#pragma unroll
    for (int k = 0; k < 4; k++) {
        bufA[k] = xg1p[k * GG + row0];
        bufB[k] = xg1p[k * GG + row1];
    }

    // ---- layer 1 ----
    for (int t0 = 0; t0 < TT; t0 += 4) {
#pragma unroll
        for (int s = 0; s < 4; s++) {
            int t = t0 + s;
            float p0 = bufA[s], p1 = bufB[s];
            int tp = t + 4;
            if (tp < TT) {                      // prefetch depth 4
                bufA[s] = xg1p[tp * GG + row0];
                bufB[s] = xg1p[tp * GG + row1];
            }
            float q0 = 0.f, q1 = 0.f;
#pragma unroll
            for (int j = 0; j < 5; j++) {
                p0 = fmaf(h[j],     w1a[j],     p0);
                q0 = fmaf(h[5 + j], w1a[5 + j], q0);
                p1 = fmaf(h[j],     w1b[j],     p1);
                q1 = fmaf(h[5 + j], w1b[5 + j], q1);
            }
            float a0 = p0 + q0, a1 = p1 + q1;
            float e0 = inv1pe2(a0);
            float e1 = inv1pe2(a1);
            float act0 = 1.0f - e0;                                    // sigmoid(i/f)
            float act1 = (L < 10) ? fmaf(-2.0f, e1, 1.0f)              // tanh(g)
                                  : (1.0f - e1);                       // sigmoid(o)
            float sf = __shfl_sync(0xffffffffu, act0, L + 10);         // sigmoid(f_j)
            float so = __shfl_sync(0xffffffffu, act1, L + 10);         // sigmoid(o_j)
            float ig = act0 * act1;                                    // sig(i)*tanh(g)
            float cn = fmaf(sf, cown, ig);
            float ec = inv1pe2(cn);
            float tc = fmaf(-2.0f, ec, 1.0f);                          // tanh(c)
            float hn = so * tc;
            if (L < 10) cown = cn;
#pragma unroll
            for (int j = 0; j < HH; j++) h[j] = __shfl_sync(0xffffffffu, hn, j);
            // produce layer-2 gate pre-activations (prescaled) on the fly
            float x2a = b2a, x2b = b2b;
#pragma unroll
            for (int j = 0; j < HH; j++) {
                x2a = fmaf(h[j], wi2a[j], x2a);
                x2b = fmaf(h[j], wi2b[j], x2b);
            }
            if (L < 20) {
                xg2p[t * GG + row0] = x2a;
                xg2p[t * GG + row1] = x2b;
            }
        }
    }

    __threadfence_block();   // make this warp's xg2 stores visible across lanes
    __syncwarp();

    // ---- layer 2 (state carries over: layer2 init state = layer1 final) ----
    float A = 0.0f, sumw = 0.0f;
    float wbuf[4];
#pragma unroll
    for (int k = 0; k < 4; k++) {
        bufA[k] = xg2p[k * GG + row0];
        bufB[k] = xg2p[k * GG + row1];
        wbuf[k] = fc2w[k];
    }
    for (int t0 = 0; t0 < TT; t0 += 4) {
#pragma unroll
        for (int s = 0; s < 4; s++) {
            int t = t0 + s;
            float p0 = bufA[s], p1 = bufB[s], wt = wbuf[s];
            int tp = t + 4;
            if (tp < TT) {
                bufA[s] = xg2p[tp * GG + row0];
                bufB[s] = xg2p[tp * GG + row1];
                wbuf[s] = fc2w[tp];
            }
            float q0 = 0.f, q1 = 0.f;
#pragma unroll
            for (int j = 0; j < 5; j++) {
                p0 = fmaf(h[j],     w2a[j],     p0);
                q0 = fmaf(h[5 + j], w2a[5 + j], q0);
                p1 = fmaf(h[j],     w2b[j],     p1);
                q1 = fmaf(h[5 + j], w2b[5 + j], q1);
            }
            float a0 = p0 + q0, a1 = p1 + q1;
            float e0 = inv1pe2(a0);
            float e1 = inv1pe2(a1);
            float act0 = 1.0f - e0;
            float act1 = (L < 10) ? fmaf(-2.0f, e1, 1.0f) : (1.0f - e1);
            float sf = __shfl_sync(0xffffffffu, act0, L + 10);
            float so = __shfl_sync(0xffffffffu, act1, L + 10);
            float ig = act0 * act1;
            float cn = fmaf(sf, cown, ig);
            float ec = inv1pe2(cn);
            float tc = fmaf(-2.0f, ec, 1.0f);
            float hn = so * tc;
            if (L < 10) cown = cn;
            sumw += wt;
            A = fmaf(wt, hn, A);               // lane j accumulates sum_t fc2w[t]*h2_j(t)
#pragma unroll
            for (int j = 0; j < HH; j++) h[j] = __shfl_sync(0xffffffffu, hn, j);
        }
    }

    // ---- fused fc1/fc2 epilogue ----
    float part = (L < 10) ? A * fc1w[L] : 0.0f;
#pragma unroll
    for (int off = 16; off; off >>= 1)
        part += __shfl_xor_sync(0xffffffffu, part, off);
    if (lane == 0)
        out[b] = part + fc1b[0] * sumw + fc2b[0];
}

// ---------------------------------------------------------------------------
// Inputs (metadata order): x, h0, c0, Wih1, Whh1, bih1, bhh1, Wih2, Whh2,
//                          bih2, bhh2, fc1_w, fc1_b, fc2_w, fc2_b
// ---------------------------------------------------------------------------
extern "C" void kernel_launch(void* const* d_in, const int* in_sizes, int n_in,
                              void* d_out, int out_size)
{
    const float* x     = (const float*)d_in[0];
    const float* h0    = (const float*)d_in[1];
    const float* c0    = (const float*)d_in[2];
    const float* Wih1  = (const float*)d_in[3];
    const float* Whh1  = (const float*)d_in[4];
    const float* bih1  = (const float*)d_in[5];
    const float* bhh1  = (const float*)d_in[6];
    const float* Wih2  = (const float*)d_in[7];
    const float* Whh2  = (const float*)d_in[8];
    const float* bih2  = (const float*)d_in[9];
    const float* bhh2  = (const float*)d_in[10];
    const float* fc1w  = (const float*)d_in[11];
    const float* fc1b  = (const float*)d_in[12];
    const float* fc2w  = (const float*)d_in[13];
    const float* fc2b  = (const float*)d_in[14];
    float* out = (float*)d_out;

    xg1_kernel<<<(BB * TT) / 128, 128>>>(x, Wih1, bih1, bhh1);
    scan_kernel<<<BB / 4, 128>>>(h0, c0, Whh1, Wih2, Whh2, bih2, bhh2,
                                 fc1w, fc1b, fc2w, fc2b, out);
}

// round 4
// speedup vs baseline: 1.4458x; 1.4458x over previous
#include <cuda_runtime.h>
#include <cstdint>
#include <cstddef>

#define BB 512
#define TT 1024
#define II 64
#define HH 10
#define GG 40

// Scratch: gate pre-activations for layer 1 and layer 2 (pre-scaled: 0.5x for
// sigmoid rows i/f/o, 1.0x for tanh rows g). Static device arrays (no allocs).
__device__ float g_xg1[(size_t)BB * TT * GG];
__device__ float g_xg2[(size_t)BB * TT * GG];

// ---------------------------------------------------------------------------
// f32x2 packed helpers (Blackwell FFMA2 path — only reachable via PTX)
// ---------------------------------------------------------------------------
__device__ __forceinline__ unsigned long long ffma2(
    unsigned long long a, unsigned long long b, unsigned long long c)
{
    unsigned long long d;
    asm("fma.rn.f32x2 %0, %1, %2, %3;" : "=l"(d) : "l"(a), "l"(b), "l"(c));
    return d;
}
__device__ __forceinline__ unsigned long long pack2(float x)
{
    unsigned long long d;
    asm("mov.b64 %0, {%1, %1};" : "=l"(d) : "f"(x));
    return d;
}

__device__ __forceinline__ float tanh_ap(float x)
{
    float y;
    asm("tanh.approx.f32 %0, %1;" : "=f"(y) : "f"(x));
    return y;
}

// ---------------------------------------------------------------------------
// Kernel 1: xg1[r,g] = scale(g)*(b[g] + sum_d x[r,d]*Wih1[g,d]), r=(b,t).
// 2 rows/thread (amortize W smem loads), FFMA2 packed math.
// ---------------------------------------------------------------------------
__global__ void __launch_bounds__(256) xg1_kernel(
    const float* __restrict__ x,
    const float* __restrict__ Wih1,
    const float* __restrict__ bih1,
    const float* __restrict__ bhh1)
{
    __shared__ __align__(16) float Wt[II * GG];   // Wt[d*GG + g], prescaled
    __shared__ __align__(16) float bs[GG];
    int tid = threadIdx.x;
    for (int i = tid; i < II * GG; i += 256) {
        int d = i / GG, g = i % GG;
        float s = (g >= 20 && g < 30) ? 1.0f : 0.5f;
        Wt[i] = Wih1[g * II + d] * s;
    }
    if (tid < GG) {
        float s = (tid >= 20 && tid < 30) ? 1.0f : 0.5f;
        bs[tid] = (bih1[tid] + bhh1[tid]) * s;
    }
    __syncthreads();

    size_t r0 = (size_t)blockIdx.x * 512 + tid;    // rows r0 and r0+256
    size_t r1 = r0 + 256;
    const float4* xr0 = (const float4*)(x + r0 * II);
    const float4* xr1 = (const float4*)(x + r1 * II);

    unsigned long long accA[20], accB[20];
    const unsigned long long* bsp = (const unsigned long long*)bs;
#pragma unroll
    for (int p = 0; p < 20; p++) { accA[p] = bsp[p]; accB[p] = bsp[p]; }

#pragma unroll 2
    for (int d4 = 0; d4 < II / 4; d4++) {
        float4 xa = xr0[d4];
        float4 xb = xr1[d4];
#pragma unroll
        for (int k = 0; k < 4; k++) {
            float fa = (k == 0) ? xa.x : (k == 1) ? xa.y : (k == 2) ? xa.z : xa.w;
            float fb = (k == 0) ? xb.x : (k == 1) ? xb.y : (k == 2) ? xb.z : xb.w;
            unsigned long long xa2 = pack2(fa);
            unsigned long long xb2 = pack2(fb);
            const ulonglong2* wr = (const ulonglong2*)(Wt + (d4 * 4 + k) * GG);
#pragma unroll
            for (int g8 = 0; g8 < 10; g8++) {      // 10 x LDS.128 = 20 pairs
                ulonglong2 w = wr[g8];
                accA[g8 * 2 + 0] = ffma2(xa2, w.x, accA[g8 * 2 + 0]);
                accA[g8 * 2 + 1] = ffma2(xa2, w.y, accA[g8 * 2 + 1]);
                accB[g8 * 2 + 0] = ffma2(xb2, w.x, accB[g8 * 2 + 0]);
                accB[g8 * 2 + 1] = ffma2(xb2, w.y, accB[g8 * 2 + 1]);
            }
        }
    }

    ulonglong2* oA = (ulonglong2*)(g_xg1 + r0 * GG);
    ulonglong2* oB = (ulonglong2*)(g_xg1 + r1 * GG);
#pragma unroll
    for (int p = 0; p < 10; p++) {
        oA[p] = make_ulonglong2(accA[p * 2], accA[p * 2 + 1]);
        oB[p] = make_ulonglong2(accB[p * 2], accB[p * 2 + 1]);
    }
}

// ---------------------------------------------------------------------------
// Kernel 2: warp-per-batch sequential scan, layer1 -> (xg2 on the fly) ->
// layer2 -> fused fc1/fc2 epilogue. MUFU.TANH activations:
//   sigmoid(pre) with prescaled a=0.5*pre:  fma(tanh(a), 0.5, 0.5)
//   tanh(x): tanh.approx(x)
// Lane L (<20) owns gate rows L (i/f) and L+20 (g/o); c_j owned by lane j.
// ---------------------------------------------------------------------------
__global__ void __launch_bounds__(128) scan_kernel(
    const float* __restrict__ h0,   const float* __restrict__ c0,
    const float* __restrict__ Whh1, const float* __restrict__ Wih2,
    const float* __restrict__ Whh2, const float* __restrict__ bih2,
    const float* __restrict__ bhh2, const float* __restrict__ fc1w,
    const float* __restrict__ fc1b, const float* __restrict__ fc2w,
    const float* __restrict__ fc2b, float* __restrict__ out)
{
    const int warp = threadIdx.x >> 5;
    const int lane = threadIdx.x & 31;
    const int b = blockIdx.x * 4 + warp;           // 128 blocks x 4 warps = 512
    const int L = lane;
    const int row0 = (L < 20) ? L : 0;             // lanes >=20 shadow lane 0
    const int row1 = row0 + 20;
    const bool isg = (L < 10);                     // row1 is g (tanh) for L<10
    const float s0 = 0.5f;
    const float s1 = isg ? 1.0f : 0.5f;

    float w1a[HH], w1b[HH], w2a[HH], w2b[HH], wi2a[HH], wi2b[HH];
#pragma unroll
    for (int j = 0; j < HH; j++) {
        w1a[j]  = Whh1[row0 * HH + j] * s0;
        w1b[j]  = Whh1[row1 * HH + j] * s1;
        w2a[j]  = Whh2[row0 * HH + j] * s0;
        w2b[j]  = Whh2[row1 * HH + j] * s1;
        wi2a[j] = Wih2[row0 * HH + j] * s0;
        wi2b[j] = Wih2[row1 * HH + j] * s1;
    }
    const float b2a = (bih2[row0] + bhh2[row0]) * s0;
    const float b2b = (bih2[row1] + bhh2[row1]) * s1;

    float h[HH], cown;
#pragma unroll
    for (int j = 0; j < HH; j++) h[j] = h0[b * HH + j];
    cown = (L < HH) ? c0[b * HH + L] : 0.0f;

    const float* xg1p = g_xg1 + (size_t)b * TT * GG;
    float*       xg2p = g_xg2 + (size_t)b * TT * GG;

    float bufA[8], bufB[8];
#pragma unroll
    for (int k = 0; k < 8; k++) {
        bufA[k] = xg1p[k * GG + row0];
        bufB[k] = xg1p[k * GG + row1];
    }

    // ---- layer 1 ----
    for (int t0 = 0; t0 < TT; t0 += 8) {
#pragma unroll
        for (int s = 0; s < 8; s++) {
            int t = t0 + s;
            float p0 = bufA[s], p1 = bufB[s];
            int tp = t + 8;                        // prefetch depth 8
            if (tp < TT) {
                bufA[s] = xg1p[tp * GG + row0];
                bufB[s] = xg1p[tp * GG + row1];
            }
            float q0 = 0.f, q1 = 0.f;
#pragma unroll
            for (int j = 0; j < 5; j++) {
                p0 = fmaf(h[j],     w1a[j],     p0);
                q0 = fmaf(h[5 + j], w1a[5 + j], q0);
                p1 = fmaf(h[j],     w1b[j],     p1);
                q1 = fmaf(h[5 + j], w1b[5 + j], q1);
            }
            float a0 = p0 + q0, a1 = p1 + q1;
            float t0a = tanh_ap(a0);
            float t1a = tanh_ap(a1);
            float act0 = fmaf(t0a, 0.5f, 0.5f);                   // sigmoid(i/f)
            float act1 = isg ? t1a : fmaf(t1a, 0.5f, 0.5f);       // tanh(g)/sig(o)
            float sf = __shfl_sync(0xffffffffu, act0, L + 10);    // sigmoid(f_j)
            float so = __shfl_sync(0xffffffffu, act1, L + 10);    // sigmoid(o_j)
            float ig = act0 * act1;                               // sig(i)*tanh(g)
            float cn = fmaf(sf, cown, ig);
            float tc = tanh_ap(cn);                               // tanh(c)
            float hn = so * tc;
            if (L < 10) cown = cn;
#pragma unroll
            for (int j = 0; j < HH; j++) h[j] = __shfl_sync(0xffffffffu, hn, j);
            // layer-2 gate pre-activations (prescaled), on the fly
            float x2a = b2a, x2b = b2b;
#pragma unroll
            for (int j = 0; j < HH; j++) {
                x2a = fmaf(h[j], wi2a[j], x2a);
                x2b = fmaf(h[j], wi2b[j], x2b);
            }
            if (L < 20) {
                xg2p[t * GG + row0] = x2a;
                xg2p[t * GG + row1] = x2b;
            }
        }
    }

    __threadfence_block();   // xg2 stores visible across lanes of this warp
    __syncwarp();

    // ---- layer 2 (init state = layer-1 final state) ----
    float A = 0.0f, sumw = 0.0f;
    float wbuf[8];
#pragma unroll
    for (int k = 0; k < 8; k++) {
        bufA[k] = xg2p[k * GG + row0];
        bufB[k] = xg2p[k * GG + row1];
        wbuf[k] = fc2w[k];
    }
    for (int t0 = 0; t0 < TT; t0 += 8) {
#pragma unroll
        for (int s = 0; s < 8; s++) {
            int t = t0 + s;
            float p0 = bufA[s], p1 = bufB[s], wt = wbuf[s];
            int tp = t + 8;
            if (tp < TT) {
                bufA[s] = xg2p[tp * GG + row0];
                bufB[s] = xg2p[tp * GG + row1];
                wbuf[s] = fc2w[tp];
            }
            float q0 = 0.f, q1 = 0.f;
#pragma unroll
            for (int j = 0; j < 5; j++) {
                p0 = fmaf(h[j],     w2a[j],     p0);
                q0 = fmaf(h[5 + j], w2a[5 + j], q0);
                p1 = fmaf(h[j],     w2b[j],     p1);
                q1 = fmaf(h[5 + j], w2b[5 + j], q1);
            }
            float a0 = p0 + q0, a1 = p1 + q1;
            float t0a = tanh_ap(a0);
            float t1a = tanh_ap(a1);
            float act0 = fmaf(t0a, 0.5f, 0.5f);
            float act1 = isg ? t1a : fmaf(t1a, 0.5f, 0.5f);
            float sf = __shfl_sync(0xffffffffu, act0, L + 10);
            float so = __shfl_sync(0xffffffffu, act1, L + 10);
            float ig = act0 * act1;
            float cn = fmaf(sf, cown, ig);
            float tc = tanh_ap(cn);
            float hn = so * tc;
            if (L < 10) cown = cn;
            sumw += wt;
            A = fmaf(wt, hn, A);          // lane j: sum_t fc2w[t]*h2_j(t)
#pragma unroll
            for (int j = 0; j < HH; j++) h[j] = __shfl_sync(0xffffffffu, hn, j);
        }
    }

    // ---- fused fc1/fc2 epilogue ----
    float part = (L < 10) ? A * fc1w[L] : 0.0f;
#pragma unroll
    for (int off = 16; off; off >>= 1)
        part += __shfl_xor_sync(0xffffffffu, part, off);
    if (lane == 0)
        out[b] = part + fc1b[0] * sumw + fc2b[0];
}

// ---------------------------------------------------------------------------
// Inputs (metadata order): x, h0, c0, Wih1, Whh1, bih1, bhh1, Wih2, Whh2,
//                          bih2, bhh2, fc1_w, fc1_b, fc2_w, fc2_b
// ---------------------------------------------------------------------------
extern "C" void kernel_launch(void* const* d_in, const int* in_sizes, int n_in,
                              void* d_out, int out_size)
{
    const float* x     = (const float*)d_in[0];
    const float* h0    = (const float*)d_in[1];
    const float* c0    = (const float*)d_in[2];
    const float* Wih1  = (const float*)d_in[3];
    const float* Whh1  = (const float*)d_in[4];
    const float* bih1  = (const float*)d_in[5];
    const float* bhh1  = (const float*)d_in[6];
    const float* Wih2  = (const float*)d_in[7];
    const float* Whh2  = (const float*)d_in[8];
    const float* bih2  = (const float*)d_in[9];
    const float* bhh2  = (const float*)d_in[10];
    const float* fc1w  = (const float*)d_in[11];
    const float* fc1b  = (const float*)d_in[12];
    const float* fc2w  = (const float*)d_in[13];
    const float* fc2b  = (const float*)d_in[14];
    float* out = (float*)d_out;

    xg1_kernel<<<(BB * TT) / 512, 256>>>(x, Wih1, bih1, bhh1);
    scan_kernel<<<BB / 4, 128>>>(h0, c0, Whh1, Wih2, Whh2, bih2, bhh2,
                                 fc1w, fc1b, fc2w, fc2b, out);
}